// round 13
// baseline (speedup 1.0000x reference)
#include <cuda_runtime.h>
#include <cuda_bf16.h>
#include <cstdint>

#define OUT_F 4096
#define IN_F  4096
#define TOKENS 8192

// Static device scratch: dequantized W (32 MB bf16) + x narrowed to bf16 (64 MB)
__device__ __align__(16) __nv_bfloat16 g_W[(size_t)OUT_F * IN_F];
__device__ __align__(16) __nv_bfloat16 g_X[(size_t)TOKENS * IN_F];

// ---------------------------------------------------------------------------
// Kernel 1: NF4 dequant -> bf16 (validated byte-level in R7, passing since R8).
// ---------------------------------------------------------------------------
__global__ void nf4_dequant_kernel(const int* __restrict__ pw,
                                   const float* __restrict__ scales,
                                   const float* __restrict__ table) {
    __shared__ float t[16];
    if (threadIdx.x < 16) t[threadIdx.x] = table[threadIdx.x];
    __syncthreads();

    int gid = blockIdx.x * blockDim.x + threadIdx.x;
    int4 p = reinterpret_cast<const int4*>(pw)[gid];
    float s = scales[gid >> 3];

    int v[4] = {p.x, p.y, p.z, p.w};
    union { __nv_bfloat16 h[8]; uint4 vec; } o;
#pragma unroll
    for (int j = 0; j < 4; ++j) {
        o.h[2 * j]     = __float2bfloat16(t[v[j] & 15] * s);
        o.h[2 * j + 1] = __float2bfloat16(t[(v[j] >> 4) & 15] * s);
    }
    *reinterpret_cast<uint4*>(&g_W[(size_t)gid * 8]) = o.vec;
}

// ---------------------------------------------------------------------------
// Kernel 2: x narrow f32 -> bf16 (values already bf16-rounded).
// ---------------------------------------------------------------------------
__global__ void x_convert_kernel(const float* __restrict__ xf) {
    size_t gid = (size_t)blockIdx.x * blockDim.x + threadIdx.x;
    const float4* src = reinterpret_cast<const float4*>(xf) + gid * 2;
    float4 a = src[0];
    float4 b = src[1];
    union { __nv_bfloat16 h[8]; uint4 vec; } o;
    o.h[0] = __float2bfloat16(a.x); o.h[1] = __float2bfloat16(a.y);
    o.h[2] = __float2bfloat16(a.z); o.h[3] = __float2bfloat16(a.w);
    o.h[4] = __float2bfloat16(b.x); o.h[5] = __float2bfloat16(b.y);
    o.h[6] = __float2bfloat16(b.z); o.h[7] = __float2bfloat16(b.w);
    *reinterpret_cast<uint4*>(&g_X[gid * 8]) = o.vec;
}

// ---------------------------------------------------------------------------
// Kernel 3: PERSISTENT bf16 GEMM via mma.sync.
// 296 CTAs (2/SM), each walks tiles bid, bid+296, ... over 2048 tiles.
// The cp.async chunk pipeline is CONTINUOUS across tile boundaries: prefetch
// for the next tile's first chunks issues while the current tile's last MMAs
// run, eliminating per-tile prologue refill bubbles.
// CTA tile 128x128x64, 128 thr (2Mx2N warps, warp 64x64), 3 stages (96 KB).
// ---------------------------------------------------------------------------
#define BM 128
#define BN 128
#define BK 64
#define STAGES 3
#define KT_PER_TILE (IN_F / BK)              // 64
#define NTILES ((TOKENS / BM) * (OUT_F / BN))// 2048
#define A_BYTES (BM * BK * 2)                // 16384
#define B_BYTES (BN * BK * 2)                // 16384
#define STAGE_BYTES (A_BYTES + B_BYTES)      // 32768
#define DYN_SMEM (STAGES * STAGE_BYTES)      // 98304
#define GRID_P 296                           // 2 per SM x 148 SMs

__device__ __forceinline__ uint32_t swz(uint32_t row, uint32_t chunk) {
    return row * 128u + ((chunk ^ (row & 7u)) * 16u);
}
__device__ __forceinline__ void cpa16(uint32_t dst, const void* src) {
    asm volatile("cp.async.cg.shared.global [%0], [%1], 16;\n" :: "r"(dst), "l"(src));
}
__device__ __forceinline__ void ldsm_x4(uint32_t& r0, uint32_t& r1,
                                        uint32_t& r2, uint32_t& r3, uint32_t addr) {
    asm volatile("ldmatrix.sync.aligned.m8n8.x4.shared.b16 {%0,%1,%2,%3}, [%4];\n"
                 : "=r"(r0), "=r"(r1), "=r"(r2), "=r"(r3) : "r"(addr));
}

// Issue one chunk (A+B K-slab) of a given tile into a given stage slot.
__device__ __forceinline__ void issue_chunk(int tile, int kt, uint32_t slotBase,
                                            int tid) {
    const int m0 = (tile >> 5) * BM;
    const int n0 = (tile & 31) * BN;
    const __nv_bfloat16* gA = g_X + (size_t)m0 * IN_F + kt * BK;
    const __nv_bfloat16* gB = g_W + (size_t)n0 * IN_F + kt * BK;
    const uint32_t bB = slotBase + A_BYTES;
#pragma unroll
    for (int i = 0; i < 8; ++i) {
        int idx = tid + i * 128;
        uint32_t row = idx >> 3, c = idx & 7;
        cpa16(slotBase + swz(row, c), gA + (size_t)row * IN_F + c * 8);
    }
#pragma unroll
    for (int i = 0; i < 8; ++i) {
        int idx = tid + i * 128;
        uint32_t row = idx >> 3, c = idx & 7;
        cpa16(bB + swz(row, c), gB + (size_t)row * IN_F + c * 8);
    }
    asm volatile("cp.async.commit_group;\n");
}

__global__ __launch_bounds__(128, 2) void mma_gemm_kernel(float* __restrict__ O) {
    extern __shared__ __align__(1024) char dyn[];
    const uint32_t base = (uint32_t)__cvta_generic_to_shared(dyn);

    const int tid  = threadIdx.x;
    const int warp = tid >> 5;
    const int lane = tid & 31;
    const int wm   = warp >> 1;            // 0..1  (M)
    const int wn   = warp & 1;             // 0..1  (N)
    const int bid  = blockIdx.x;

    // ldmatrix lane addressing (mapping validated since R10)
    const uint32_t a_row = wm * 64 + (lane & 15);
    const uint32_t a_chp = (lane >> 4);
    const uint32_t b_row = wn * 64 + ((lane >> 4) & 1) * 8 + (lane & 7);
    const uint32_t b_chp = (lane >> 3) & 1;

    const int ntiles = (NTILES - bid + GRID_P - 1) / GRID_P;  // tiles for this CTA
    const long total_chunks = (long)ntiles * KT_PER_TILE;

    float acc[4][8][4];
#pragma unroll
    for (int mi = 0; mi < 4; ++mi)
#pragma unroll
        for (int ni = 0; ni < 8; ++ni)
#pragma unroll
            for (int c = 0; c < 4; ++c) acc[mi][ni][c] = 0.f;

    // continuous chunk-stream state
    long issued = 0;
    int  issueSlot = 0;   // stage slot of next issue
    int  curSlot   = 0;   // stage slot of next consume

    // prologue: 2 chunks in flight
#pragma unroll
    for (int p = 0; p < 2; ++p) {
        issue_chunk(bid + GRID_P * (int)(issued >> 6), (int)(issued & 63),
                    base + issueSlot * STAGE_BYTES, tid);
        issued++;
        issueSlot = (issueSlot + 1) % STAGES;
    }

    uint32_t fa[2][4][4], fb[2][8][2];
    long consumed = 0;

    for (int lt = 0; lt < ntiles; ++lt) {
        const int tile = bid + GRID_P * lt;
        const int m0 = (tile >> 5) * BM;
        const int n0 = (tile & 31) * BN;

        for (int kt = 0; kt < KT_PER_TILE; ++kt) {
            // wait for chunk 'consumed' (FIFO): pending after = issued-consumed-1
            if (issued - consumed >= 2) { asm volatile("cp.async.wait_group 1;\n"); }
            else                        { asm volatile("cp.async.wait_group 0;\n"); }
            __syncthreads();   // stage curSlot ready for ALL threads; orders
                               // prior-stage reads before the overwrite below.

            const uint32_t aB = base + curSlot * STAGE_BYTES;
            const uint32_t bB = aB + A_BYTES;

            if (issued < total_chunks) {
                issue_chunk(bid + GRID_P * (int)(issued >> 6), (int)(issued & 63),
                            base + issueSlot * STAGE_BYTES, tid);
                issued++;
                issueSlot = (issueSlot + 1) % STAGES;
            }

            // fragments ks=0 -> buffer 0
#pragma unroll
            for (int mi = 0; mi < 4; ++mi) {
                uint32_t row = a_row + mi * 16;
                ldsm_x4(fa[0][mi][0], fa[0][mi][1], fa[0][mi][2], fa[0][mi][3],
                        aB + swz(row, a_chp));
            }
#pragma unroll
            for (int p = 0; p < 4; ++p) {
                uint32_t row = b_row + p * 16;
                ldsm_x4(fb[0][2 * p][0], fb[0][2 * p][1],
                        fb[0][2 * p + 1][0], fb[0][2 * p + 1][1],
                        bB + swz(row, b_chp));
            }

#pragma unroll
            for (int ks = 0; ks < 4; ++ks) {
                const int cur = ks & 1, nxt = cur ^ 1;
                if (ks < 3) {
                    const uint32_t kch = (ks + 1) * 2;
#pragma unroll
                    for (int mi = 0; mi < 4; ++mi) {
                        uint32_t row = a_row + mi * 16;
                        ldsm_x4(fa[nxt][mi][0], fa[nxt][mi][1],
                                fa[nxt][mi][2], fa[nxt][mi][3],
                                aB + swz(row, kch + a_chp));
                    }
#pragma unroll
                    for (int p = 0; p < 4; ++p) {
                        uint32_t row = b_row + p * 16;
                        ldsm_x4(fb[nxt][2 * p][0], fb[nxt][2 * p][1],
                                fb[nxt][2 * p + 1][0], fb[nxt][2 * p + 1][1],
                                bB + swz(row, kch + b_chp));
                    }
                }
#pragma unroll
                for (int ni = 0; ni < 8; ++ni)
#pragma unroll
                    for (int mi = 0; mi < 4; ++mi) {
                        asm volatile(
                            "mma.sync.aligned.m16n8k16.row.col.f32.bf16.bf16.f32 "
                            "{%0,%1,%2,%3}, {%4,%5,%6,%7}, {%8,%9}, {%0,%1,%2,%3};\n"
                            : "+f"(acc[mi][ni][0]), "+f"(acc[mi][ni][1]),
                              "+f"(acc[mi][ni][2]), "+f"(acc[mi][ni][3])
                            : "r"(fa[cur][mi][0]), "r"(fa[cur][mi][1]),
                              "r"(fa[cur][mi][2]), "r"(fa[cur][mi][3]),
                              "r"(fb[cur][ni][0]), "r"(fb[cur][ni][1]));
                    }
            }
            consumed++;
            curSlot = (curSlot + 1) % STAGES;
        }

        // ---- tile epilogue: register drain (smem untouched -> no sync) ----
        const int grp = lane >> 2;
        const int tq  = lane & 3;
#pragma unroll
        for (int mi = 0; mi < 4; ++mi) {
            const int row0 = m0 + wm * 64 + mi * 16 + grp;
#pragma unroll
            for (int ni = 0; ni < 8; ++ni) {
                const int col = n0 + wn * 64 + ni * 8 + tq * 2;
                float2 v01, v23;
                v01.x = __bfloat162float(__float2bfloat16(acc[mi][ni][0]));
                v01.y = __bfloat162float(__float2bfloat16(acc[mi][ni][1]));
                v23.x = __bfloat162float(__float2bfloat16(acc[mi][ni][2]));
                v23.y = __bfloat162float(__float2bfloat16(acc[mi][ni][3]));
                *reinterpret_cast<float2*>(&O[(size_t)row0 * OUT_F + col])       = v01;
                *reinterpret_cast<float2*>(&O[(size_t)(row0 + 8) * OUT_F + col]) = v23;
                acc[mi][ni][0] = 0.f; acc[mi][ni][1] = 0.f;
                acc[mi][ni][2] = 0.f; acc[mi][ni][3] = 0.f;
            }
        }
    }
}

// ---------------------------------------------------------------------------
extern "C" void kernel_launch(void* const* d_in, const int* in_sizes, int n_in,
                              void* d_out, int out_size) {
    const float* x      = nullptr;
    const int*   packed = nullptr;
    const float* scales = nullptr;
    const float* table  = nullptr;

    for (int i = 0; i < n_in; ++i) {
        long n = in_sizes[i];
        if      (n == (long)TOKENS * IN_F)        x      = (const float*)d_in[i];
        else if (n == (long)OUT_F * IN_F / 2)     packed = (const int*)d_in[i];
        else if (n == (long)OUT_F * IN_F / 64)    scales = (const float*)d_in[i];
        else if (n == 16)                         table  = (const float*)d_in[i];
    }

    float* out = (float*)d_out;

    const int n_packed = OUT_F * IN_F / 2;
    nf4_dequant_kernel<<<n_packed / 4 / 256, 256>>>(packed, scales, table);

    const long n_x = (long)TOKENS * IN_F;
    x_convert_kernel<<<(int)(n_x / 8 / 256), 256>>>(x);

    static bool attr_set = false;
    if (!attr_set) {
        cudaFuncSetAttribute(mma_gemm_kernel,
                             cudaFuncAttributeMaxDynamicSharedMemorySize, DYN_SMEM);
        attr_set = true;
    }
    mma_gemm_kernel<<<GRID_P, 128, DYN_SMEM>>>(out);
}

// round 14
// speedup vs baseline: 1.0173x; 1.0173x over previous
#include <cuda_runtime.h>
#include <cuda_bf16.h>
#include <cstdint>

#define OUT_F 4096
#define IN_F  4096
#define TOKENS 8192

// Static device scratch: dequantized W (32 MB bf16) + x narrowed to bf16 (64 MB)
__device__ __align__(16) __nv_bfloat16 g_W[(size_t)OUT_F * IN_F];
__device__ __align__(16) __nv_bfloat16 g_X[(size_t)TOKENS * IN_F];

// ---------------------------------------------------------------------------
// Kernel 1 (fused prep): NF4 dequant -> g_W  AND  x f32->bf16 -> g_X.
// Grid-stride over both jobs; one launch, full-machine bandwidth.
// Dequant semantics byte-validated in R7, passing since R8.
// ---------------------------------------------------------------------------
#define N_PACKED_G (OUT_F * IN_F / 2 / 4)        // 2,097,152 int4-groups
#define N_XCONV_G  (TOKENS * IN_F / 8)           // 4,194,304 8-elem groups

__global__ __launch_bounds__(256) void prep_kernel(const float* __restrict__ xf,
                                                   const int* __restrict__ pw,
                                                   const float* __restrict__ scales,
                                                   const float* __restrict__ table) {
    __shared__ float t[16];
    if (threadIdx.x < 16) t[threadIdx.x] = table[threadIdx.x];
    __syncthreads();

    const int nth = gridDim.x * blockDim.x;
    const int tid0 = blockIdx.x * blockDim.x + threadIdx.x;

    // --- dequant: each group = 4 packed int32 = 8 weights ---
    for (int gid = tid0; gid < N_PACKED_G; gid += nth) {
        int4 p = reinterpret_cast<const int4*>(pw)[gid];
        float s = scales[gid >> 3];
        int v[4] = {p.x, p.y, p.z, p.w};
        union { __nv_bfloat16 h[8]; uint4 vec; } o;
#pragma unroll
        for (int j = 0; j < 4; ++j) {
            o.h[2 * j]     = __float2bfloat16(t[v[j] & 15] * s);
            o.h[2 * j + 1] = __float2bfloat16(t[(v[j] >> 4) & 15] * s);
        }
        *reinterpret_cast<uint4*>(&g_W[(size_t)gid * 8]) = o.vec;
    }

    // --- x convert: each group = 8 f32 -> 8 bf16 ---
    for (int gid = tid0; gid < N_XCONV_G; gid += nth) {
        const float4* src = reinterpret_cast<const float4*>(xf) + (size_t)gid * 2;
        float4 a = src[0];
        float4 b = src[1];
        union { __nv_bfloat16 h[8]; uint4 vec; } o;
        o.h[0] = __float2bfloat16(a.x); o.h[1] = __float2bfloat16(a.y);
        o.h[2] = __float2bfloat16(a.z); o.h[3] = __float2bfloat16(a.w);
        o.h[4] = __float2bfloat16(b.x); o.h[5] = __float2bfloat16(b.y);
        o.h[6] = __float2bfloat16(b.z); o.h[7] = __float2bfloat16(b.w);
        *reinterpret_cast<uint4*>(&g_X[(size_t)gid * 8]) = o.vec;
    }
}

// ---------------------------------------------------------------------------
// Kernel 2: bf16 GEMM via mma.sync (exact R12 revert — best known config).
// CTA 128x128x64, 128 thr (2Mx2N warps, warp 64x64), 3 stages, 2 CTAs/SM.
// Swizzle: 128B rows of 8x16B chunks, chunk ^= (row & 7).
// ---------------------------------------------------------------------------
#define BM 128
#define BN 128
#define BK 64
#define STAGES 3
#define NT (IN_F / BK)                       // 64
#define A_BYTES (BM * BK * 2)                // 16384
#define B_BYTES (BN * BK * 2)                // 16384
#define STAGE_BYTES (A_BYTES + B_BYTES)      // 32768
#define DYN_SMEM (STAGES * STAGE_BYTES)      // 98304

__device__ __forceinline__ uint32_t swz(uint32_t row, uint32_t chunk) {
    return row * 128u + ((chunk ^ (row & 7u)) * 16u);
}
__device__ __forceinline__ void cpa16(uint32_t dst, const void* src) {
    asm volatile("cp.async.cg.shared.global [%0], [%1], 16;\n" :: "r"(dst), "l"(src));
}
__device__ __forceinline__ void ldsm_x4(uint32_t& r0, uint32_t& r1,
                                        uint32_t& r2, uint32_t& r3, uint32_t addr) {
    asm volatile("ldmatrix.sync.aligned.m8n8.x4.shared.b16 {%0,%1,%2,%3}, [%4];\n"
                 : "=r"(r0), "=r"(r1), "=r"(r2), "=r"(r3) : "r"(addr));
}

__device__ __forceinline__ void issue_stage(const __nv_bfloat16* __restrict__ gA,
                                            const __nv_bfloat16* __restrict__ gB,
                                            int kc, uint32_t aB, uint32_t bB, int tid) {
#pragma unroll
    for (int i = 0; i < 8; ++i) {
        int idx = tid + i * 128;
        uint32_t row = idx >> 3, c = idx & 7;
        cpa16(aB + swz(row, c), gA + (size_t)row * IN_F + kc + c * 8);
    }
#pragma unroll
    for (int i = 0; i < 8; ++i) {
        int idx = tid + i * 128;
        uint32_t row = idx >> 3, c = idx & 7;
        cpa16(bB + swz(row, c), gB + (size_t)row * IN_F + kc + c * 8);
    }
    asm volatile("cp.async.commit_group;\n");
}

__global__ __launch_bounds__(128, 2) void mma_gemm_kernel(float* __restrict__ O) {
    extern __shared__ __align__(1024) char dyn[];
    const uint32_t base = (uint32_t)__cvta_generic_to_shared(dyn);

    const int tid  = threadIdx.x;
    const int warp = tid >> 5;
    const int lane = tid & 31;
    const int wm   = warp >> 1;            // 0..1  (M)
    const int wn   = warp & 1;             // 0..1  (N)

    const int n0 = (blockIdx.x & 31) * BN;
    const int m0 = (blockIdx.x >> 5) * BM;

    const __nv_bfloat16* gA = g_X + (size_t)m0 * IN_F;
    const __nv_bfloat16* gB = g_W + (size_t)n0 * IN_F;

    const uint32_t a_row = wm * 64 + (lane & 15);
    const uint32_t a_chp = (lane >> 4);
    const uint32_t b_row = wn * 64 + ((lane >> 4) & 1) * 8 + (lane & 7);
    const uint32_t b_chp = (lane >> 3) & 1;

    float acc[4][8][4];
#pragma unroll
    for (int mi = 0; mi < 4; ++mi)
#pragma unroll
        for (int ni = 0; ni < 8; ++ni)
#pragma unroll
            for (int c = 0; c < 4; ++c) acc[mi][ni][c] = 0.f;

    issue_stage(gA, gB, 0,  base,               base + A_BYTES, tid);
    issue_stage(gA, gB, BK, base + STAGE_BYTES, base + STAGE_BYTES + A_BYTES, tid);

    uint32_t fa[2][4][4], fb[2][8][2];

    for (int kt = 0; kt < NT; ++kt) {
        if (kt < NT - 1) { asm volatile("cp.async.wait_group 1;\n"); }
        else             { asm volatile("cp.async.wait_group 0;\n"); }
        __syncthreads();   // stage kt ready for ALL threads; orders prior-stage
                           // reads before the prefetch below that overwrites it.

        const int st = kt % STAGES;
        const uint32_t aB = base + st * STAGE_BYTES;
        const uint32_t bB = aB + A_BYTES;

        if (kt + 2 < NT) {
            const int st2 = (kt + 2) % STAGES;
            issue_stage(gA, gB, (kt + 2) * BK,
                        base + st2 * STAGE_BYTES,
                        base + st2 * STAGE_BYTES + A_BYTES, tid);
        }

#pragma unroll
        for (int mi = 0; mi < 4; ++mi) {
            uint32_t row = a_row + mi * 16;
            ldsm_x4(fa[0][mi][0], fa[0][mi][1], fa[0][mi][2], fa[0][mi][3],
                    aB + swz(row, a_chp));
        }
#pragma unroll
        for (int p = 0; p < 4; ++p) {
            uint32_t row = b_row + p * 16;
            ldsm_x4(fb[0][2 * p][0], fb[0][2 * p][1],
                    fb[0][2 * p + 1][0], fb[0][2 * p + 1][1],
                    bB + swz(row, b_chp));
        }

#pragma unroll
        for (int ks = 0; ks < 4; ++ks) {
            const int cur = ks & 1, nxt = cur ^ 1;
            if (ks < 3) {
                const uint32_t kch = (ks + 1) * 2;
#pragma unroll
                for (int mi = 0; mi < 4; ++mi) {
                    uint32_t row = a_row + mi * 16;
                    ldsm_x4(fa[nxt][mi][0], fa[nxt][mi][1],
                            fa[nxt][mi][2], fa[nxt][mi][3],
                            aB + swz(row, kch + a_chp));
                }
#pragma unroll
                for (int p = 0; p < 4; ++p) {
                    uint32_t row = b_row + p * 16;
                    ldsm_x4(fb[nxt][2 * p][0], fb[nxt][2 * p][1],
                            fb[nxt][2 * p + 1][0], fb[nxt][2 * p + 1][1],
                            bB + swz(row, kch + b_chp));
                }
            }
#pragma unroll
            for (int ni = 0; ni < 8; ++ni)
#pragma unroll
                for (int mi = 0; mi < 4; ++mi) {
                    asm volatile(
                        "mma.sync.aligned.m16n8k16.row.col.f32.bf16.bf16.f32 "
                        "{%0,%1,%2,%3}, {%4,%5,%6,%7}, {%8,%9}, {%0,%1,%2,%3};\n"
                        : "+f"(acc[mi][ni][0]), "+f"(acc[mi][ni][1]),
                          "+f"(acc[mi][ni][2]), "+f"(acc[mi][ni][3])
                        : "r"(fa[cur][mi][0]), "r"(fa[cur][mi][1]),
                          "r"(fa[cur][mi][2]), "r"(fa[cur][mi][3]),
                          "r"(fb[cur][ni][0]), "r"(fb[cur][ni][1]));
                }
        }
    }

    // Epilogue: bf16-round, widen to f32, float2 stores
    const int grp = lane >> 2;
    const int tq  = lane & 3;
#pragma unroll
    for (int mi = 0; mi < 4; ++mi) {
        const int row0 = m0 + wm * 64 + mi * 16 + grp;
#pragma unroll
        for (int ni = 0; ni < 8; ++ni) {
            const int col = n0 + wn * 64 + ni * 8 + tq * 2;
            float2 v01, v23;
            v01.x = __bfloat162float(__float2bfloat16(acc[mi][ni][0]));
            v01.y = __bfloat162float(__float2bfloat16(acc[mi][ni][1]));
            v23.x = __bfloat162float(__float2bfloat16(acc[mi][ni][2]));
            v23.y = __bfloat162float(__float2bfloat16(acc[mi][ni][3]));
            *reinterpret_cast<float2*>(&O[(size_t)row0 * OUT_F + col])       = v01;
            *reinterpret_cast<float2*>(&O[(size_t)(row0 + 8) * OUT_F + col]) = v23;
        }
    }
}

// ---------------------------------------------------------------------------
extern "C" void kernel_launch(void* const* d_in, const int* in_sizes, int n_in,
                              void* d_out, int out_size) {
    const float* x      = nullptr;
    const int*   packed = nullptr;
    const float* scales = nullptr;
    const float* table  = nullptr;

    for (int i = 0; i < n_in; ++i) {
        long n = in_sizes[i];
        if      (n == (long)TOKENS * IN_F)        x      = (const float*)d_in[i];
        else if (n == (long)OUT_F * IN_F / 2)     packed = (const int*)d_in[i];
        else if (n == (long)OUT_F * IN_F / 64)    scales = (const float*)d_in[i];
        else if (n == 16)                         table  = (const float*)d_in[i];
    }

    float* out = (float*)d_out;

    prep_kernel<<<2048, 256>>>(x, packed, scales, table);

    static bool attr_set = false;
    if (!attr_set) {
        cudaFuncSetAttribute(mma_gemm_kernel,
                             cudaFuncAttributeMaxDynamicSharedMemorySize, DYN_SMEM);
        attr_set = true;
    }
    // grid: 64 M-blocks x 32 N-blocks, N fastest (x row-block L2 reuse)
    mma_gemm_kernel<<<(TOKENS / BM) * (OUT_F / BN), 128, DYN_SMEM>>>(out);
}

// round 15
// speedup vs baseline: 1.1040x; 1.0852x over previous
#include <cuda_runtime.h>
#include <cuda_bf16.h>
#include <cstdint>

#define OUT_F 4096
#define IN_F  4096
#define TOKENS 8192

// Static device scratch: dequantized W (32 MB bf16) + x narrowed to bf16 (64 MB)
__device__ __align__(16) __nv_bfloat16 g_W[(size_t)OUT_F * IN_F];
__device__ __align__(16) __nv_bfloat16 g_X[(size_t)TOKENS * IN_F];

// ---------------------------------------------------------------------------
// Kernel 1 (fused prep): NF4 dequant -> g_W  AND  x f32->bf16 -> g_X.
// ---------------------------------------------------------------------------
#define N_PACKED_G (OUT_F * IN_F / 2 / 4)        // 2,097,152 int4-groups
#define N_XCONV_G  (TOKENS * IN_F / 8)           // 4,194,304 8-elem groups

__global__ __launch_bounds__(256) void prep_kernel(const float* __restrict__ xf,
                                                   const int* __restrict__ pw,
                                                   const float* __restrict__ scales,
                                                   const float* __restrict__ table) {
    __shared__ float t[16];
    if (threadIdx.x < 16) t[threadIdx.x] = table[threadIdx.x];
    __syncthreads();

    const int nth = gridDim.x * blockDim.x;
    const int tid0 = blockIdx.x * blockDim.x + threadIdx.x;

    for (int gid = tid0; gid < N_PACKED_G; gid += nth) {
        int4 p = reinterpret_cast<const int4*>(pw)[gid];
        float s = scales[gid >> 3];
        int v[4] = {p.x, p.y, p.z, p.w};
        union { __nv_bfloat16 h[8]; uint4 vec; } o;
#pragma unroll
        for (int j = 0; j < 4; ++j) {
            o.h[2 * j]     = __float2bfloat16(t[v[j] & 15] * s);
            o.h[2 * j + 1] = __float2bfloat16(t[(v[j] >> 4) & 15] * s);
        }
        *reinterpret_cast<uint4*>(&g_W[(size_t)gid * 8]) = o.vec;
    }

    for (int gid = tid0; gid < N_XCONV_G; gid += nth) {
        const float4* src = reinterpret_cast<const float4*>(xf) + (size_t)gid * 2;
        float4 a = src[0];
        float4 b = src[1];
        union { __nv_bfloat16 h[8]; uint4 vec; } o;
        o.h[0] = __float2bfloat16(a.x); o.h[1] = __float2bfloat16(a.y);
        o.h[2] = __float2bfloat16(a.z); o.h[3] = __float2bfloat16(a.w);
        o.h[4] = __float2bfloat16(b.x); o.h[5] = __float2bfloat16(b.y);
        o.h[6] = __float2bfloat16(b.z); o.h[7] = __float2bfloat16(b.w);
        *reinterpret_cast<uint4*>(&g_X[(size_t)gid * 8]) = o.vec;
    }
}

// ---------------------------------------------------------------------------
// Kernel 2: bf16 GEMM via mma.sync.  CTA 128x128x64, 128 thr (2Mx2N warps,
// warp 64x64), 3 stages, 2 CTAs/SM.  Per-tile stream reordered so the 16
// cp.async issues sit BEHIND the ks0 MMA batch (off the critical path).
// ---------------------------------------------------------------------------
#define BM 128
#define BN 128
#define BK 64
#define STAGES 3
#define NT (IN_F / BK)                       // 64
#define A_BYTES (BM * BK * 2)                // 16384
#define B_BYTES (BN * BK * 2)                // 16384
#define STAGE_BYTES (A_BYTES + B_BYTES)      // 32768
#define DYN_SMEM (STAGES * STAGE_BYTES)      // 98304

__device__ __forceinline__ uint32_t swz(uint32_t row, uint32_t chunk) {
    return row * 128u + ((chunk ^ (row & 7u)) * 16u);
}
__device__ __forceinline__ void cpa16(uint32_t dst, const void* src) {
    asm volatile("cp.async.cg.shared.global [%0], [%1], 16;\n" :: "r"(dst), "l"(src));
}
__device__ __forceinline__ void ldsm_x4(uint32_t& r0, uint32_t& r1,
                                        uint32_t& r2, uint32_t& r3, uint32_t addr) {
    asm volatile("ldmatrix.sync.aligned.m8n8.x4.shared.b16 {%0,%1,%2,%3}, [%4];\n"
                 : "=r"(r0), "=r"(r1), "=r"(r2), "=r"(r3) : "r"(addr));
}

__device__ __forceinline__ void issue_stage(const __nv_bfloat16* __restrict__ gA,
                                            const __nv_bfloat16* __restrict__ gB,
                                            int kc, uint32_t aB, uint32_t bB, int tid) {
#pragma unroll
    for (int i = 0; i < 8; ++i) {
        int idx = tid + i * 128;
        uint32_t row = idx >> 3, c = idx & 7;
        cpa16(aB + swz(row, c), gA + (size_t)row * IN_F + kc + c * 8);
    }
#pragma unroll
    for (int i = 0; i < 8; ++i) {
        int idx = tid + i * 128;
        uint32_t row = idx >> 3, c = idx & 7;
        cpa16(bB + swz(row, c), gB + (size_t)row * IN_F + kc + c * 8);
    }
    asm volatile("cp.async.commit_group;\n");
}

__global__ __launch_bounds__(128, 2) void mma_gemm_kernel(float* __restrict__ O) {
    extern __shared__ __align__(1024) char dyn[];
    const uint32_t base = (uint32_t)__cvta_generic_to_shared(dyn);

    const int tid  = threadIdx.x;
    const int warp = tid >> 5;
    const int lane = tid & 31;
    const int wm   = warp >> 1;
    const int wn   = warp & 1;

    const int n0 = (blockIdx.x & 31) * BN;
    const int m0 = (blockIdx.x >> 5) * BM;

    const __nv_bfloat16* gA = g_X + (size_t)m0 * IN_F;
    const __nv_bfloat16* gB = g_W + (size_t)n0 * IN_F;

    const uint32_t a_row = wm * 64 + (lane & 15);
    const uint32_t a_chp = (lane >> 4);
    const uint32_t b_row = wn * 64 + ((lane >> 4) & 1) * 8 + (lane & 7);
    const uint32_t b_chp = (lane >> 3) & 1;

    float acc[4][8][4];
#pragma unroll
    for (int mi = 0; mi < 4; ++mi)
#pragma unroll
        for (int ni = 0; ni < 8; ++ni)
#pragma unroll
            for (int c = 0; c < 4; ++c) acc[mi][ni][c] = 0.f;

    issue_stage(gA, gB, 0,  base,               base + A_BYTES, tid);
    issue_stage(gA, gB, BK, base + STAGE_BYTES, base + STAGE_BYTES + A_BYTES, tid);

    uint32_t fa[2][4][4], fb[2][8][2];

    for (int kt = 0; kt < NT; ++kt) {
        if (kt < NT - 1) { asm volatile("cp.async.wait_group 1;\n"); }
        else             { asm volatile("cp.async.wait_group 0;\n"); }
        __syncthreads();   // stage kt ready for ALL threads; orders prior-stage
                           // reads before the prefetch below that overwrites it.

        const int st = kt % STAGES;
        const uint32_t aB = base + st * STAGE_BYTES;
        const uint32_t bB = aB + A_BYTES;

        // ---- ks0 fragments FIRST (critical path) ----
#pragma unroll
        for (int mi = 0; mi < 4; ++mi) {
            uint32_t row = a_row + mi * 16;
            ldsm_x4(fa[0][mi][0], fa[0][mi][1], fa[0][mi][2], fa[0][mi][3],
                    aB + swz(row, a_chp));
        }
#pragma unroll
        for (int p = 0; p < 4; ++p) {
            uint32_t row = b_row + p * 16;
            ldsm_x4(fb[0][2 * p][0], fb[0][2 * p][1],
                    fb[0][2 * p + 1][0], fb[0][2 * p + 1][1],
                    bB + swz(row, b_chp));
        }

        // ---- ks0 MMA batch: fills the tensor pipe ----
#pragma unroll
        for (int ni = 0; ni < 8; ++ni)
#pragma unroll
            for (int mi = 0; mi < 4; ++mi) {
                asm volatile(
                    "mma.sync.aligned.m16n8k16.row.col.f32.bf16.bf16.f32 "
                    "{%0,%1,%2,%3}, {%4,%5,%6,%7}, {%8,%9}, {%0,%1,%2,%3};\n"
                    : "+f"(acc[mi][ni][0]), "+f"(acc[mi][ni][1]),
                      "+f"(acc[mi][ni][2]), "+f"(acc[mi][ni][3])
                    : "r"(fa[0][mi][0]), "r"(fa[0][mi][1]),
                      "r"(fa[0][mi][2]), "r"(fa[0][mi][3]),
                      "r"(fb[0][ni][0]), "r"(fb[0][ni][1]));
            }

        // ---- prefetch kt+2: issue burst hidden behind ks0 MMA drain ----
        if (kt + 2 < NT) {
            const int st2 = (kt + 2) % STAGES;
            issue_stage(gA, gB, (kt + 2) * BK,
                        base + st2 * STAGE_BYTES,
                        base + st2 * STAGE_BYTES + A_BYTES, tid);
        }

        // ---- ks 1..3: load frags, then MMA ----
#pragma unroll
        for (int ks = 1; ks < 4; ++ks) {
            const int buf = ks & 1;
            const uint32_t kch = ks * 2;
#pragma unroll
            for (int mi = 0; mi < 4; ++mi) {
                uint32_t row = a_row + mi * 16;
                ldsm_x4(fa[buf][mi][0], fa[buf][mi][1],
                        fa[buf][mi][2], fa[buf][mi][3],
                        aB + swz(row, kch + a_chp));
            }
#pragma unroll
            for (int p = 0; p < 4; ++p) {
                uint32_t row = b_row + p * 16;
                ldsm_x4(fb[buf][2 * p][0], fb[buf][2 * p][1],
                        fb[buf][2 * p + 1][0], fb[buf][2 * p + 1][1],
                        bB + swz(row, kch + b_chp));
            }
#pragma unroll
            for (int ni = 0; ni < 8; ++ni)
#pragma unroll
                for (int mi = 0; mi < 4; ++mi) {
                    asm volatile(
                        "mma.sync.aligned.m16n8k16.row.col.f32.bf16.bf16.f32 "
                        "{%0,%1,%2,%3}, {%4,%5,%6,%7}, {%8,%9}, {%0,%1,%2,%3};\n"
                        : "+f"(acc[mi][ni][0]), "+f"(acc[mi][ni][1]),
                          "+f"(acc[mi][ni][2]), "+f"(acc[mi][ni][3])
                        : "r"(fa[buf][mi][0]), "r"(fa[buf][mi][1]),
                          "r"(fa[buf][mi][2]), "r"(fa[buf][mi][3]),
                          "r"(fb[buf][ni][0]), "r"(fb[buf][ni][1]));
                }
        }
    }

    // Epilogue: bf16-round, widen to f32, float2 stores
    const int grp = lane >> 2;
    const int tq  = lane & 3;
#pragma unroll
    for (int mi = 0; mi < 4; ++mi) {
        const int row0 = m0 + wm * 64 + mi * 16 + grp;
#pragma unroll
        for (int ni = 0; ni < 8; ++ni) {
            const int col = n0 + wn * 64 + ni * 8 + tq * 2;
            float2 v01, v23;
            v01.x = __bfloat162float(__float2bfloat16(acc[mi][ni][0]));
            v01.y = __bfloat162float(__float2bfloat16(acc[mi][ni][1]));
            v23.x = __bfloat162float(__float2bfloat16(acc[mi][ni][2]));
            v23.y = __bfloat162float(__float2bfloat16(acc[mi][ni][3]));
            *reinterpret_cast<float2*>(&O[(size_t)row0 * OUT_F + col])       = v01;
            *reinterpret_cast<float2*>(&O[(size_t)(row0 + 8) * OUT_F + col]) = v23;
        }
    }
}

// ---------------------------------------------------------------------------
extern "C" void kernel_launch(void* const* d_in, const int* in_sizes, int n_in,
                              void* d_out, int out_size) {
    const float* x      = nullptr;
    const int*   packed = nullptr;
    const float* scales = nullptr;
    const float* table  = nullptr;

    for (int i = 0; i < n_in; ++i) {
        long n = in_sizes[i];
        if      (n == (long)TOKENS * IN_F)        x      = (const float*)d_in[i];
        else if (n == (long)OUT_F * IN_F / 2)     packed = (const int*)d_in[i];
        else if (n == (long)OUT_F * IN_F / 64)    scales = (const float*)d_in[i];
        else if (n == 16)                         table  = (const float*)d_in[i];
    }

    float* out = (float*)d_out;

    prep_kernel<<<2048, 256>>>(x, packed, scales, table);

    static bool attr_set = false;
    if (!attr_set) {
        cudaFuncSetAttribute(mma_gemm_kernel,
                             cudaFuncAttributeMaxDynamicSharedMemorySize, DYN_SMEM);
        attr_set = true;
    }
    mma_gemm_kernel<<<(TOKENS / BM) * (OUT_F / BN), 128, DYN_SMEM>>>(out);
}